// round 9
// baseline (speedup 1.0000x reference)
#include <cuda_runtime.h>
#include <cuda_bf16.h>
#include <math.h>
#include <stdint.h>

// Problem constants
#define BATCH 2
#define SEQ   2048
#define CDIM  1024
#define NHEAD 16
#define HDIM  64
#define C3    (3*CDIM)          // 3072
#define MROWS (BATCH*SEQ)       // 4096

// Scratch (no cudaMalloc allowed)
__device__ float g_qkv[(size_t)MROWS * C3];       // [B,T,3,H,D] tf32, k-dim pi-permuted
__device__ float g_attn[(size_t)MROWS * CDIM];    // [B,T,C] tf32, pi-permuted
__device__ float g_xr[(size_t)MROWS * CDIM];      // x tf32, pi-permuted
__device__ float g_wqkvr[(size_t)CDIM * C3];      // Wqkv tf32 (logical layout)
__device__ float g_woutr[(size_t)CDIM * CDIM];    // Wout tf32 (logical layout)

// pi within aligned 8-blocks: logical k -> stored pos 2*(k%4)+(k/4)
// => logical pair (k, k+4) lands at adjacent stored positions (2*(k%4), +1).
__device__ __forceinline__ int pcol(int c) {
    return (c & ~7) | ((c & 3) << 1) | ((c & 4) >> 2);
}

__device__ __forceinline__ uint32_t f2tf32(float f) {
    uint32_t r;
    asm("cvt.rna.tf32.f32 %0, %1;" : "=r"(r) : "f"(f));
    return r;
}
__device__ __forceinline__ float fexp2(float x) {
    float y;
    asm("ex2.approx.f32 %0, %1;" : "=f"(y) : "f"(x));
    return y;
}
__device__ __forceinline__ uint32_t smem_u32(const void* p) {
    uint32_t a;
    asm("{ .reg .u64 t; cvta.to.shared.u64 t, %1; cvt.u32.u64 %0, t; }" : "=r"(a) : "l"(p));
    return a;
}
#define CP_ASYNC16(dst_u32, src_ptr) \
    asm volatile("cp.async.cg.shared.global [%0], [%1], 16;" :: "r"(dst_u32), "l"(src_ptr) : "memory")
#define CP_COMMIT() asm volatile("cp.async.commit_group;" ::: "memory")
#define CP_WAIT0()  asm volatile("cp.async.wait_group 0;" ::: "memory")
#define CP_WAIT1()  asm volatile("cp.async.wait_group 1;" ::: "memory")

__device__ __forceinline__ void mma_tf32(float c[4], const uint32_t a[4], const uint32_t b[2]) {
    asm volatile(
        "mma.sync.aligned.m16n8k8.row.col.f32.tf32.tf32.f32 "
        "{%0,%1,%2,%3}, {%4,%5,%6,%7}, {%8,%9}, {%0,%1,%2,%3};"
        : "+f"(c[0]), "+f"(c[1]), "+f"(c[2]), "+f"(c[3])
        : "r"(a[0]), "r"(a[1]), "r"(a[2]), "r"(a[3]), "r"(b[0]), "r"(b[1]));
}

// ---------------------------------------------------------------------------
// Fused pre-pass: x -> tf32 + pi-permute; weights -> tf32 plain.
// Each thread handles one aligned 8-float group.
// ---------------------------------------------------------------------------
#define XG (MROWS * CDIM / 8)
#define W1G (CDIM * C3 / 8)
#define W2G (CDIM * CDIM / 8)
#define TOTG (XG + W1G + W2G)

__global__ __launch_bounds__(256)
void prepass_kernel(const float* __restrict__ x,  float* __restrict__ xr,
                    const float* __restrict__ w1, float* __restrict__ w1r,
                    const float* __restrict__ w2, float* __restrict__ w2r)
{
    int i = blockIdx.x * blockDim.x + threadIdx.x;
    if (i >= TOTG) return;
    bool permute;
    const float4* src;
    float4* dst;
    int j;
    if (i < XG)            { src = (const float4*)x;  dst = (float4*)xr;  j = i;            permute = true;  }
    else if (i < XG + W1G) { src = (const float4*)w1; dst = (float4*)w1r; j = i - XG;       permute = false; }
    else                   { src = (const float4*)w2; dst = (float4*)w2r; j = i - XG - W1G; permute = false; }
    float4 v0 = src[2 * j];
    float4 v1 = src[2 * j + 1];
    float4 o0, o1;
    if (permute) {
        // stored order: k0,k4,k1,k5 | k2,k6,k3,k7
        o0.x = __uint_as_float(f2tf32(v0.x)); o0.y = __uint_as_float(f2tf32(v1.x));
        o0.z = __uint_as_float(f2tf32(v0.y)); o0.w = __uint_as_float(f2tf32(v1.y));
        o1.x = __uint_as_float(f2tf32(v0.z)); o1.y = __uint_as_float(f2tf32(v1.z));
        o1.z = __uint_as_float(f2tf32(v0.w)); o1.w = __uint_as_float(f2tf32(v1.w));
    } else {
        o0.x = __uint_as_float(f2tf32(v0.x)); o0.y = __uint_as_float(f2tf32(v0.y));
        o0.z = __uint_as_float(f2tf32(v0.z)); o0.w = __uint_as_float(f2tf32(v0.w));
        o1.x = __uint_as_float(f2tf32(v1.x)); o1.y = __uint_as_float(f2tf32(v1.y));
        o1.z = __uint_as_float(f2tf32(v1.z)); o1.w = __uint_as_float(f2tf32(v1.w));
    }
    dst[2 * j]     = o0;
    dst[2 * j + 1] = o1;
}

// ---------------------------------------------------------------------------
// tf32 mma.sync GEMM + bias: C[M,N] = A[M,K] @ B[K,N] + bias[N]
// A [M][K] tf32 PI-PERMUTED on k; B [K][N] tf32 logical. cp.async 3-stage,
// ONE barrier per K-chunk. A-fragments via LDS.64 (pi pairs).
// RND: round + pi-permute output (for tensors feeding later mma stages).
// ---------------------------------------------------------------------------
#define GBM 128
#define GBN 128
#define GBK 32
#define A_STRIDE 36
#define B_STRIDE 136
#define A_FLOATS (GBM * A_STRIDE)
#define B_FLOATS (GBK * B_STRIDE)
#define STG_FLOATS (A_FLOATS + B_FLOATS)
#define GEMM_SMEM (3 * STG_FLOATS * 4)

template<bool RND>
__global__ __launch_bounds__(256)
void gemm_tc_kernel(const float* __restrict__ A,
                    const float* __restrict__ B,
                    const float* __restrict__ bias,
                    float* __restrict__ C,
                    int M, int N, int K)
{
    extern __shared__ float smem[];
    const int tid = threadIdx.x;
    const int wid = tid >> 5;
    const int l   = tid & 31;
    const int warpM = wid >> 2;
    const int warpN = wid & 3;
    const int rowbase = blockIdx.y * GBM;
    const int colbase = blockIdx.x * GBN;

    const uint32_t smb = smem_u32(smem);

    float acc[4][4][4];
    #pragma unroll
    for (int i = 0; i < 4; i++)
        #pragma unroll
        for (int j = 0; j < 4; j++)
            #pragma unroll
            for (int q = 0; q < 4; q++) acc[i][j][q] = 0.f;

    const int a_r = tid >> 3, a_c = (tid & 7) * 4;
    const int b_r = tid >> 5, b_c = (tid & 31) * 4;

    const int S = K / GBK;

    auto load_stage = [&](int stg, int k0) {
        const uint32_t sa = smb + stg * STG_FLOATS * 4;
        const uint32_t sb = sa + A_FLOATS * 4;
        #pragma unroll
        for (int it = 0; it < 4; it++) {
            const int r = it * 32 + a_r;
            CP_ASYNC16(sa + (uint32_t)(r * A_STRIDE + a_c) * 4,
                       A + (size_t)(rowbase + r) * K + k0 + a_c);
        }
        #pragma unroll
        for (int it = 0; it < 4; it++) {
            const int r = it * 8 + b_r;
            CP_ASYNC16(sb + (uint32_t)(r * B_STRIDE + b_c) * 4,
                       B + (size_t)(k0 + r) * N + colbase + b_c);
        }
        CP_COMMIT();
    };

    load_stage(0, 0);
    load_stage(1, GBK);

    const int arow0 = warpM * 64 + (l >> 2);
    const int bcol0 = warpN * 32 + (l >> 2);
    const int kfrag = (l & 3);

    for (int s = 0; s < S; s++) {
        if (s + 1 < S) { CP_WAIT1(); } else { CP_WAIT0(); }
        __syncthreads();
        if (s + 2 < S) load_stage((s + 2) % 3, (s + 2) * GBK);

        const float* as = smem + (s % 3) * STG_FLOATS;
        const float* bs = as + A_FLOATS;
        #pragma unroll
        for (int ks = 0; ks < 4; ks++) {
            const int kpos = ks * 8 + 2 * kfrag;      // pi-permuted pair position
            uint32_t af[4][4], bf[4][2];
            #pragma unroll
            for (int i = 0; i < 4; i++) {
                const int r = arow0 + i * 16;
                float2 lo = *(const float2*)(as + (r    ) * A_STRIDE + kpos);
                float2 hi = *(const float2*)(as + (r + 8) * A_STRIDE + kpos);
                af[i][0] = __float_as_uint(lo.x);
                af[i][1] = __float_as_uint(hi.x);
                af[i][2] = __float_as_uint(lo.y);
                af[i][3] = __float_as_uint(hi.y);
            }
            #pragma unroll
            for (int j = 0; j < 4; j++) {
                const int n = bcol0 + j * 8;
                bf[j][0] = __float_as_uint(bs[(ks * 8 + kfrag    ) * B_STRIDE + n]);
                bf[j][1] = __float_as_uint(bs[(ks * 8 + kfrag + 4) * B_STRIDE + n]);
            }
            #pragma unroll
            for (int i = 0; i < 4; i++)
                #pragma unroll
                for (int j = 0; j < 4; j++)
                    mma_tf32(acc[i][j], af[i], bf[j]);
        }
    }

    const int erow = rowbase + warpM * 64 + (l >> 2);
    const int ecol = colbase + warpN * 32 + 2 * (l & 3);
    #pragma unroll
    for (int i = 0; i < 4; i++) {
        #pragma unroll
        for (int j = 0; j < 4; j++) {
            const int r0 = erow + i * 16;
            const int c0 = ecol + j * 8;
            const float b0 = bias[c0], b1 = bias[c0 + 1];
            if (RND) {
                const int p0 = pcol(c0), p1 = pcol(c0 + 1);
                C[(size_t)r0 * N + p0]       = __uint_as_float(f2tf32(acc[i][j][0] + b0));
                C[(size_t)r0 * N + p1]       = __uint_as_float(f2tf32(acc[i][j][1] + b1));
                C[(size_t)(r0 + 8) * N + p0] = __uint_as_float(f2tf32(acc[i][j][2] + b0));
                C[(size_t)(r0 + 8) * N + p1] = __uint_as_float(f2tf32(acc[i][j][3] + b1));
            } else {
                float2 v0 = { acc[i][j][0] + b0, acc[i][j][1] + b1 };
                float2 v1 = { acc[i][j][2] + b0, acc[i][j][3] + b1 };
                *(float2*)(C + (size_t)r0 * N + c0)       = v0;
                *(float2*)(C + (size_t)(r0 + 8) * N + c0) = v1;
            }
        }
    }
}

// ---------------------------------------------------------------------------
// Tensor-core flash attention. qkv is tf32 + pi-permuted on d within heads.
// K-fragments via LDS.64 (pi pairs); Q via float2; V column index remapped.
// cp.async double-buffered K/V with ONE barrier per tile.
// CTA = 128 q rows of one (b,h); 8 warps x 16 rows. K-tile = 64 keys.
// ---------------------------------------------------------------------------
#define AQ 128
#define AK 64
#define KS_STRIDE 68
#define VS_STRIDE 72
#define PS_STRIDE 68
#define KS_FLOATS (AK * KS_STRIDE)
#define VS_FLOATS (AK * VS_STRIDE)
#define KV_FLOATS (KS_FLOATS + VS_FLOATS)
#define PS_FLOATS (8 * 16 * PS_STRIDE)
#define ATTN_SMEM ((2 * KV_FLOATS + PS_FLOATS) * 4)   // 106496 B

__global__ __launch_bounds__(256)
void attn_tc_kernel(const float* __restrict__ qkv, float* __restrict__ out)
{
    extern __shared__ float sm[];
    float* Psm = sm + 2 * KV_FLOATS;

    const int qtile = blockIdx.x;
    const int h   = blockIdx.y;
    const int b   = blockIdx.z;
    const int tid = threadIdx.x;
    const int wid = tid >> 5;
    const int l   = tid & 31;
    const int g   = l >> 2;
    const int t   = l & 3;
    const int qb  = qtile * AQ;
    const int rg  = qb + wid * 16 + g;
    const int gp  = ((g & 3) << 1) | (g >> 2);   // pi position of g within 8

    const float SC = 0.18033688011112042f;   // (1/sqrt(64)) * log2(e)
    float* Pw = Psm + wid * (16 * PS_STRIDE);
    const uint32_t smb = smem_u32(sm);

    auto load_kv = [&](int stg, int kb) {
        const uint32_t kbuf = smb + stg * KV_FLOATS * 4;
        const uint32_t vbuf = kbuf + KS_FLOATS * 4;
        #pragma unroll
        for (int it = 0; it < 4; it++) {
            const int idx = it * 256 + tid;
            const int r = idx >> 4;
            const int c = (idx & 15) * 4;
            const float* src = qkv + (size_t)(b * SEQ + kb + r) * C3 + h * HDIM + c;
            CP_ASYNC16(kbuf + (uint32_t)(r * KS_STRIDE + c) * 4, src + CDIM);
            CP_ASYNC16(vbuf + (uint32_t)(r * VS_STRIDE + c) * 4, src + 2 * CDIM);
        }
        CP_COMMIT();
    };

    // Q fragments (pi pairs -> float2 loads), scale folded
    uint32_t qa[8][4];
    {
        const float* Qr  = qkv + (size_t)(b * SEQ + rg    ) * C3 + h * HDIM;
        const float* Qr8 = qkv + (size_t)(b * SEQ + rg + 8) * C3 + h * HDIM;
        #pragma unroll
        for (int ks = 0; ks < 8; ks++) {
            float2 q0 = *(const float2*)(Qr  + ks * 8 + 2 * t);
            float2 q8 = *(const float2*)(Qr8 + ks * 8 + 2 * t);
            qa[ks][0] = f2tf32(q0.x * SC);
            qa[ks][1] = f2tf32(q8.x * SC);
            qa[ks][2] = f2tf32(q0.y * SC);
            qa[ks][3] = f2tf32(q8.y * SC);
        }
    }

    float O[8][4];
    #pragma unroll
    for (int nb = 0; nb < 8; nb++)
        #pragma unroll
        for (int q = 0; q < 4; q++) O[nb][q] = 0.f;
    float m0 = -INFINITY, m1 = -INFINITY, l0 = 0.f, l1 = 0.f;

    const int ntiles = (qb + AQ) / AK;

    load_kv(0, 0);

    for (int ti = 0; ti < ntiles; ti++) {
        CP_WAIT0();
        __syncthreads();
        if (ti + 1 < ntiles) load_kv((ti + 1) & 1, (ti + 1) * AK);

        const float* Ksm = sm + (ti & 1) * KV_FLOATS;
        const float* Vsm = Ksm + KS_FLOATS;
        const int kb = ti * AK;

        // S = Q @ K^T  (K pi pairs via LDS.64)
        float sc[8][4];
        #pragma unroll
        for (int nb = 0; nb < 8; nb++) {
            sc[nb][0] = 0.f; sc[nb][1] = 0.f; sc[nb][2] = 0.f; sc[nb][3] = 0.f;
            const float* Krow = Ksm + (nb * 8 + g) * KS_STRIDE + 2 * t;
            #pragma unroll
            for (int ks = 0; ks < 8; ks++) {
                float2 kv2 = *(const float2*)(Krow + ks * 8);
                uint32_t bf[2] = { __float_as_uint(kv2.x), __float_as_uint(kv2.y) };
                mma_tf32(sc[nb], qa[ks], bf);
            }
        }

        // Causal mask only on diagonal-overlapping tiles
        const bool needmask = (kb + AK - 1) > (qb + wid * 16);
        float tm0 = -INFINITY, tm1 = -INFINITY;
        if (needmask) {
            #pragma unroll
            for (int nb = 0; nb < 8; nb++) {
                const int k0 = kb + nb * 8 + 2 * t;
                if (k0     > rg    ) sc[nb][0] = -INFINITY;
                if (k0 + 1 > rg    ) sc[nb][1] = -INFINITY;
                if (k0     > rg + 8) sc[nb][2] = -INFINITY;
                if (k0 + 1 > rg + 8) sc[nb][3] = -INFINITY;
                tm0 = fmaxf(tm0, fmaxf(sc[nb][0], sc[nb][1]));
                tm1 = fmaxf(tm1, fmaxf(sc[nb][2], sc[nb][3]));
            }
        } else {
            #pragma unroll
            for (int nb = 0; nb < 8; nb++) {
                tm0 = fmaxf(tm0, fmaxf(sc[nb][0], sc[nb][1]));
                tm1 = fmaxf(tm1, fmaxf(sc[nb][2], sc[nb][3]));
            }
        }
        tm0 = fmaxf(tm0, __shfl_xor_sync(0xffffffffu, tm0, 1));
        tm0 = fmaxf(tm0, __shfl_xor_sync(0xffffffffu, tm0, 2));
        tm1 = fmaxf(tm1, __shfl_xor_sync(0xffffffffu, tm1, 1));
        tm1 = fmaxf(tm1, __shfl_xor_sync(0xffffffffu, tm1, 2));

        const float nm0 = fmaxf(m0, tm0);
        const float nm1 = fmaxf(m1, tm1);
        const float c0 = fexp2(m0 - nm0);
        const float c1 = fexp2(m1 - nm1);
        l0 *= c0; l1 *= c1;
        #pragma unroll
        for (int nb = 0; nb < 8; nb++) {
            O[nb][0] *= c0; O[nb][1] *= c0;
            O[nb][2] *= c1; O[nb][3] *= c1;
        }
        m0 = nm0; m1 = nm1;

        #pragma unroll
        for (int nb = 0; nb < 8; nb++) {
            float p0 = fexp2(sc[nb][0] - m0);
            float p1 = fexp2(sc[nb][1] - m0);
            float p2 = fexp2(sc[nb][2] - m1);
            float p3 = fexp2(sc[nb][3] - m1);
            l0 += p0 + p1;
            l1 += p2 + p3;
            uint2 u0 = { f2tf32(p0), f2tf32(p1) };
            uint2 u1 = { f2tf32(p2), f2tf32(p3) };
            *(uint2*)(Pw + (g    ) * PS_STRIDE + nb * 8 + 2 * t) = u0;
            *(uint2*)(Pw + (g + 8) * PS_STRIDE + nb * 8 + 2 * t) = u1;
        }
        __syncwarp();

        // O += P @ V  (V columns pi-remapped: gp)
        #pragma unroll
        for (int ks = 0; ks < 8; ks++) {
            uint32_t pa[4];
            pa[0] = __float_as_uint(Pw[(g    ) * PS_STRIDE + ks * 8 + t    ]);
            pa[1] = __float_as_uint(Pw[(g + 8) * PS_STRIDE + ks * 8 + t    ]);
            pa[2] = __float_as_uint(Pw[(g    ) * PS_STRIDE + ks * 8 + t + 4]);
            pa[3] = __float_as_uint(Pw[(g + 8) * PS_STRIDE + ks * 8 + t + 4]);
            #pragma unroll
            for (int nb = 0; nb < 8; nb++) {
                uint32_t bf[2];
                bf[0] = __float_as_uint(Vsm[(ks * 8 + t    ) * VS_STRIDE + nb * 8 + gp]);
                bf[1] = __float_as_uint(Vsm[(ks * 8 + t + 4) * VS_STRIDE + nb * 8 + gp]);
                mma_tf32(O[nb], pa, bf);
            }
        }
        __syncwarp();
    }

    l0 += __shfl_xor_sync(0xffffffffu, l0, 1);
    l0 += __shfl_xor_sync(0xffffffffu, l0, 2);
    l1 += __shfl_xor_sync(0xffffffffu, l1, 1);
    l1 += __shfl_xor_sync(0xffffffffu, l1, 2);
    const float inv0 = 1.f / l0;
    const float inv1 = 1.f / l1;

    // Write g_attn pi-permuted (feeds GEMM3's A operand)
    float* out0 = out + (size_t)(b * SEQ + rg    ) * CDIM + h * HDIM;
    float* out8 = out + (size_t)(b * SEQ + rg + 8) * CDIM + h * HDIM;
    #pragma unroll
    for (int nb = 0; nb < 8; nb++) {
        const int c = nb * 8 + 2 * t;
        const int p0 = pcol(c), p1 = pcol(c + 1);
        out0[p0] = __uint_as_float(f2tf32(O[nb][0] * inv0));
        out0[p1] = __uint_as_float(f2tf32(O[nb][1] * inv0));
        out8[p0] = __uint_as_float(f2tf32(O[nb][2] * inv1));
        out8[p1] = __uint_as_float(f2tf32(O[nb][3] * inv1));
    }
}

// ---------------------------------------------------------------------------
// Launch
// ---------------------------------------------------------------------------
extern "C" void kernel_launch(void* const* d_in, const int* in_sizes, int n_in,
                              void* d_out, int out_size)
{
    const float* x    = (const float*)d_in[0];
    const float* Wqkv = (const float*)d_in[1];
    const float* bqkv = (const float*)d_in[2];
    const float* Wout = (const float*)d_in[3];
    const float* bout = (const float*)d_in[4];
    float* out = (float*)d_out;

    float *qkv, *attn, *xr, *wqkvr, *woutr;
    cudaGetSymbolAddress((void**)&qkv,   g_qkv);
    cudaGetSymbolAddress((void**)&attn,  g_attn);
    cudaGetSymbolAddress((void**)&xr,    g_xr);
    cudaGetSymbolAddress((void**)&wqkvr, g_wqkvr);
    cudaGetSymbolAddress((void**)&woutr, g_woutr);

    static bool attr_set = false;
    if (!attr_set) {
        cudaFuncSetAttribute(gemm_tc_kernel<true>,  cudaFuncAttributeMaxDynamicSharedMemorySize, GEMM_SMEM);
        cudaFuncSetAttribute(gemm_tc_kernel<false>, cudaFuncAttributeMaxDynamicSharedMemorySize, GEMM_SMEM);
        cudaFuncSetAttribute(attn_tc_kernel, cudaFuncAttributeMaxDynamicSharedMemorySize, ATTN_SMEM);
        attr_set = true;
    }

    // 0) Pre-pass: x -> tf32+pi; weights -> tf32
    prepass_kernel<<<(TOTG + 255) / 256, 256>>>(x, xr, Wqkv, wqkvr, Wout, woutr);

    // 1) QKV projection (output tf32 + pi-permuted)
    {
        dim3 grid(C3 / GBN, MROWS / GBM);
        gemm_tc_kernel<true><<<grid, 256, GEMM_SMEM>>>(xr, wqkvr, bqkv, qkv, MROWS, C3, CDIM);
    }
    // 2) Causal flash attention -> g_attn (tf32 + pi-permuted)
    {
        dim3 grid(SEQ / AQ, NHEAD, BATCH);
        attn_tc_kernel<<<grid, 256, ATTN_SMEM>>>(qkv, attn);
    }
    // 3) Output projection (fp32, logical layout)
    {
        dim3 grid(CDIM / GBN, MROWS / GBM);
        gemm_tc_kernel<false><<<grid, 256, GEMM_SMEM>>>(attn, woutr, bout, out, MROWS, CDIM, CDIM);
    }
}

// round 10
// speedup vs baseline: 1.1390x; 1.1390x over previous
#include <cuda_runtime.h>
#include <cuda_bf16.h>
#include <math.h>
#include <stdint.h>

// Problem constants
#define BATCH 2
#define SEQ   2048
#define CDIM  1024
#define NHEAD 16
#define HDIM  64
#define C3    (3*CDIM)          // 3072
#define MROWS (BATCH*SEQ)       // 4096

// Scratch (no cudaMalloc allowed)
__device__ float g_qkv[(size_t)MROWS * C3];       // [B,T,3,H,D] (tf32-rounded)
__device__ float g_attn[(size_t)MROWS * CDIM];    // [B,T,C]     (tf32-rounded)
__device__ float g_xr[(size_t)MROWS * CDIM];      // x, tf32-rounded
__device__ float g_wqkvr[(size_t)CDIM * C3];      // Wqkv, tf32-rounded
__device__ float g_woutr[(size_t)CDIM * CDIM];    // Wout, tf32-rounded

__device__ __forceinline__ uint32_t f2tf32(float f) {
    uint32_t r;
    asm("cvt.rna.tf32.f32 %0, %1;" : "=r"(r) : "f"(f));
    return r;
}
__device__ __forceinline__ float fexp2(float x) {
    float y;
    asm("ex2.approx.f32 %0, %1;" : "=f"(y) : "f"(x));
    return y;
}
__device__ __forceinline__ uint32_t smem_u32(const void* p) {
    uint32_t a;
    asm("{ .reg .u64 t; cvta.to.shared.u64 t, %1; cvt.u32.u64 %0, t; }" : "=r"(a) : "l"(p));
    return a;
}
#define CP_ASYNC16(dst_u32, src_ptr) \
    asm volatile("cp.async.cg.shared.global [%0], [%1], 16;" :: "r"(dst_u32), "l"(src_ptr) : "memory")
#define CP_COMMIT() asm volatile("cp.async.commit_group;" ::: "memory")
#define CP_WAIT0()  asm volatile("cp.async.wait_group 0;" ::: "memory")
#define CP_WAIT1()  asm volatile("cp.async.wait_group 1;" ::: "memory")

__device__ __forceinline__ void mma_tf32(float c[4], const uint32_t a[4], const uint32_t b[2]) {
    asm volatile(
        "mma.sync.aligned.m16n8k8.row.col.f32.tf32.tf32.f32 "
        "{%0,%1,%2,%3}, {%4,%5,%6,%7}, {%8,%9}, {%0,%1,%2,%3};"
        : "+f"(c[0]), "+f"(c[1]), "+f"(c[2]), "+f"(c[3])
        : "r"(a[0]), "r"(a[1]), "r"(a[2]), "r"(a[3]), "r"(b[0]), "r"(b[1]));
}

// ---------------------------------------------------------------------------
// Fused tf32 pre-round pass over x, Wqkv, Wout (one launch)
// ---------------------------------------------------------------------------
#define RN1 (MROWS * CDIM / 4)
#define RN2 (CDIM * C3 / 4)
#define RN3 (CDIM * CDIM / 4)
#define RNT (RN1 + RN2 + RN3)

__global__ __launch_bounds__(256)
void round3_kernel(const float* __restrict__ x,    float* __restrict__ xr,
                   const float* __restrict__ w1,   float* __restrict__ w1r,
                   const float* __restrict__ w2,   float* __restrict__ w2r)
{
    int i = blockIdx.x * blockDim.x + threadIdx.x;
    const float4* src;
    float4* dst;
    int j;
    if (i < RN1)            { src = (const float4*)x;  dst = (float4*)xr;  j = i; }
    else if (i < RN1 + RN2) { src = (const float4*)w1; dst = (float4*)w1r; j = i - RN1; }
    else if (i < RNT)       { src = (const float4*)w2; dst = (float4*)w2r; j = i - RN1 - RN2; }
    else return;
    float4 v = src[j];
    float4 o;
    o.x = __uint_as_float(f2tf32(v.x));
    o.y = __uint_as_float(f2tf32(v.y));
    o.z = __uint_as_float(f2tf32(v.z));
    o.w = __uint_as_float(f2tf32(v.w));
    dst[j] = o;
}

// ---------------------------------------------------------------------------
// tf32 mma.sync GEMM + bias, cp.async 3-stage pipeline, ONE barrier/chunk.
// C[M,N] = A[M,K] @ B[K,N] + bias[N]. A,B must be tf32-pre-rounded.
// CTA 128x128, BK=32, 8 warps (2x4), warp tile 64x32. (R7 load patterns.)
// ---------------------------------------------------------------------------
#define GBM 128
#define GBN 128
#define GBK 32
#define A_STRIDE 36
#define B_STRIDE 136
#define A_FLOATS (GBM * A_STRIDE)       // 4608
#define B_FLOATS (GBK * B_STRIDE)       // 4352
#define STG_FLOATS (A_FLOATS + B_FLOATS)
#define GEMM_SMEM (3 * STG_FLOATS * 4)  // 107520 B

template<bool RND>
__global__ __launch_bounds__(256)
void gemm_tc_kernel(const float* __restrict__ A,
                    const float* __restrict__ B,
                    const float* __restrict__ bias,
                    float* __restrict__ C,
                    int M, int N, int K)
{
    extern __shared__ float smem[];
    const int tid = threadIdx.x;
    const int wid = tid >> 5;
    const int l   = tid & 31;
    const int warpM = wid >> 2;
    const int warpN = wid & 3;
    const int rowbase = blockIdx.y * GBM;
    const int colbase = blockIdx.x * GBN;

    const uint32_t smb = smem_u32(smem);

    float acc[4][4][4];
    #pragma unroll
    for (int i = 0; i < 4; i++)
        #pragma unroll
        for (int j = 0; j < 4; j++)
            #pragma unroll
            for (int q = 0; q < 4; q++) acc[i][j][q] = 0.f;

    const int a_r = tid >> 3, a_c = (tid & 7) * 4;
    const int b_r = tid >> 5, b_c = (tid & 31) * 4;

    const int S = K / GBK;

    auto load_stage = [&](int stg, int k0) {
        const uint32_t sa = smb + stg * STG_FLOATS * 4;
        const uint32_t sb = sa + A_FLOATS * 4;
        #pragma unroll
        for (int it = 0; it < 4; it++) {
            const int r = it * 32 + a_r;
            CP_ASYNC16(sa + (uint32_t)(r * A_STRIDE + a_c) * 4,
                       A + (size_t)(rowbase + r) * K + k0 + a_c);
        }
        #pragma unroll
        for (int it = 0; it < 4; it++) {
            const int r = it * 8 + b_r;
            CP_ASYNC16(sb + (uint32_t)(r * B_STRIDE + b_c) * 4,
                       B + (size_t)(k0 + r) * N + colbase + b_c);
        }
        CP_COMMIT();
    };

    load_stage(0, 0);
    load_stage(1, GBK);

    const int arow0 = warpM * 64 + (l >> 2);
    const int bcol0 = warpN * 32 + (l >> 2);
    const int kfrag = (l & 3);

    for (int s = 0; s < S; s++) {
        if (s + 1 < S) { CP_WAIT1(); } else { CP_WAIT0(); }
        __syncthreads();
        // Safe to overwrite stage (s+2)%3 now: its readers finished at the
        // barrier above (each warp's s-1 compute precedes its arrival).
        if (s + 2 < S) load_stage((s + 2) % 3, (s + 2) * GBK);

        const float* as = smem + (s % 3) * STG_FLOATS;
        const float* bs = as + A_FLOATS;
        #pragma unroll
        for (int ks = 0; ks < 4; ks++) {
            const int kk = ks * 8 + kfrag;
            uint32_t af[4][4], bf[4][2];
            #pragma unroll
            for (int i = 0; i < 4; i++) {
                const int r = arow0 + i * 16;
                af[i][0] = __float_as_uint(as[(r    ) * A_STRIDE + kk    ]);
                af[i][1] = __float_as_uint(as[(r + 8) * A_STRIDE + kk    ]);
                af[i][2] = __float_as_uint(as[(r    ) * A_STRIDE + kk + 4]);
                af[i][3] = __float_as_uint(as[(r + 8) * A_STRIDE + kk + 4]);
            }
            #pragma unroll
            for (int j = 0; j < 4; j++) {
                const int n = bcol0 + j * 8;
                bf[j][0] = __float_as_uint(bs[(ks * 8 + kfrag    ) * B_STRIDE + n]);
                bf[j][1] = __float_as_uint(bs[(ks * 8 + kfrag + 4) * B_STRIDE + n]);
            }
            #pragma unroll
            for (int i = 0; i < 4; i++)
                #pragma unroll
                for (int j = 0; j < 4; j++)
                    mma_tf32(acc[i][j], af[i], bf[j]);
        }
    }

    const int erow = rowbase + warpM * 64 + (l >> 2);
    const int ecol = colbase + warpN * 32 + 2 * (l & 3);
    #pragma unroll
    for (int i = 0; i < 4; i++) {
        #pragma unroll
        for (int j = 0; j < 4; j++) {
            const int r0 = erow + i * 16;
            const int c0 = ecol + j * 8;
            const float b0 = bias[c0], b1 = bias[c0 + 1];
            float2 v0, v1;
            if (RND) {
                v0.x = __uint_as_float(f2tf32(acc[i][j][0] + b0));
                v0.y = __uint_as_float(f2tf32(acc[i][j][1] + b1));
                v1.x = __uint_as_float(f2tf32(acc[i][j][2] + b0));
                v1.y = __uint_as_float(f2tf32(acc[i][j][3] + b1));
            } else {
                v0.x = acc[i][j][0] + b0; v0.y = acc[i][j][1] + b1;
                v1.x = acc[i][j][2] + b0; v1.y = acc[i][j][3] + b1;
            }
            *(float2*)(C + (size_t)r0 * N + c0)       = v0;
            *(float2*)(C + (size_t)(r0 + 8) * N + c0) = v1;
        }
    }
}

// ---------------------------------------------------------------------------
// Tensor-core flash attention (R7 data paths), cp.async double-buffered K/V,
// ONE barrier per tile, HEAVY-FIRST launch order (qtile reversed).
// CTA = 128 q rows of one (b,h); 8 warps x 16 rows. K-tile = 64 keys.
// ---------------------------------------------------------------------------
#define AQ 128
#define AK 64
#define KS_STRIDE 68
#define VS_STRIDE 72
#define PS_STRIDE 68
#define KS_FLOATS (AK * KS_STRIDE)
#define VS_FLOATS (AK * VS_STRIDE)
#define KV_FLOATS (KS_FLOATS + VS_FLOATS)
#define PS_FLOATS (8 * 16 * PS_STRIDE)
#define ATTN_SMEM ((2 * KV_FLOATS + PS_FLOATS) * 4)   // 106496 B

__global__ __launch_bounds__(256)
void attn_tc_kernel(const float* __restrict__ qkv, float* __restrict__ out)
{
    extern __shared__ float sm[];
    float* Psm = sm + 2 * KV_FLOATS;

    const int qtile = gridDim.x - 1 - blockIdx.x;   // heavy tiles launch first
    const int h   = blockIdx.y;
    const int b   = blockIdx.z;
    const int tid = threadIdx.x;
    const int wid = tid >> 5;
    const int l   = tid & 31;
    const int g   = l >> 2;
    const int t   = l & 3;
    const int qb  = qtile * AQ;
    const int rg  = qb + wid * 16 + g;

    const float SC = 0.18033688011112042f;   // (1/sqrt(64)) * log2(e)
    float* Pw = Psm + wid * (16 * PS_STRIDE);
    const uint32_t smb = smem_u32(sm);

    auto load_kv = [&](int stg, int kb) {
        const uint32_t kbuf = smb + stg * KV_FLOATS * 4;
        const uint32_t vbuf = kbuf + KS_FLOATS * 4;
        #pragma unroll
        for (int it = 0; it < 4; it++) {
            const int idx = it * 256 + tid;
            const int r = idx >> 4;
            const int c = (idx & 15) * 4;
            const float* src = qkv + (size_t)(b * SEQ + kb + r) * C3 + h * HDIM + c;
            CP_ASYNC16(kbuf + (uint32_t)(r * KS_STRIDE + c) * 4, src + CDIM);
            CP_ASYNC16(vbuf + (uint32_t)(r * VS_STRIDE + c) * 4, src + 2 * CDIM);
        }
        CP_COMMIT();
    };

    // Q fragments with softmax scale pre-folded (tf32-rounded)
    uint32_t qa[8][4];
    {
        const float* Qr  = qkv + (size_t)(b * SEQ + rg    ) * C3 + h * HDIM;
        const float* Qr8 = qkv + (size_t)(b * SEQ + rg + 8) * C3 + h * HDIM;
        #pragma unroll
        for (int ks = 0; ks < 8; ks++) {
            qa[ks][0] = f2tf32(Qr [ks * 8 + t]     * SC);
            qa[ks][1] = f2tf32(Qr8[ks * 8 + t]     * SC);
            qa[ks][2] = f2tf32(Qr [ks * 8 + t + 4] * SC);
            qa[ks][3] = f2tf32(Qr8[ks * 8 + t + 4] * SC);
        }
    }

    float O[8][4];
    #pragma unroll
    for (int nb = 0; nb < 8; nb++)
        #pragma unroll
        for (int q = 0; q < 4; q++) O[nb][q] = 0.f;
    float m0 = -INFINITY, m1 = -INFINITY, l0 = 0.f, l1 = 0.f;

    const int ntiles = (qb + AQ) / AK;

    load_kv(0, 0);
    if (ntiles > 1) load_kv(1, AK);

    for (int ti = 0; ti < ntiles; ti++) {
        if (ti + 1 < ntiles) { CP_WAIT1(); } else { CP_WAIT0(); }
        __syncthreads();
        // Overwrite of buffer (ti+2)&1 == ti&1 is safe only AFTER this tile's
        // reads; issue the prefetch for ti+2 at the END of the tile instead.

        const float* Ksm = sm + (ti & 1) * KV_FLOATS;
        const float* Vsm = Ksm + KS_FLOATS;
        const int kb = ti * AK;

        // S = Q @ K^T (already scaled, log2 domain)
        float sc[8][4];
        #pragma unroll
        for (int nb = 0; nb < 8; nb++) {
            sc[nb][0] = 0.f; sc[nb][1] = 0.f; sc[nb][2] = 0.f; sc[nb][3] = 0.f;
            #pragma unroll
            for (int ks = 0; ks < 8; ks++) {
                uint32_t bf[2];
                bf[0] = __float_as_uint(Ksm[(nb * 8 + g) * KS_STRIDE + ks * 8 + t    ]);
                bf[1] = __float_as_uint(Ksm[(nb * 8 + g) * KS_STRIDE + ks * 8 + t + 4]);
                mma_tf32(sc[nb], qa[ks], bf);
            }
        }

        // Causal mask only on diagonal-overlapping tiles
        const bool needmask = (kb + AK - 1) > (qb + wid * 16);
        float tm0 = -INFINITY, tm1 = -INFINITY;
        if (needmask) {
            #pragma unroll
            for (int nb = 0; nb < 8; nb++) {
                const int k0 = kb + nb * 8 + 2 * t;
                if (k0     > rg    ) sc[nb][0] = -INFINITY;
                if (k0 + 1 > rg    ) sc[nb][1] = -INFINITY;
                if (k0     > rg + 8) sc[nb][2] = -INFINITY;
                if (k0 + 1 > rg + 8) sc[nb][3] = -INFINITY;
                tm0 = fmaxf(tm0, fmaxf(sc[nb][0], sc[nb][1]));
                tm1 = fmaxf(tm1, fmaxf(sc[nb][2], sc[nb][3]));
            }
        } else {
            #pragma unroll
            for (int nb = 0; nb < 8; nb++) {
                tm0 = fmaxf(tm0, fmaxf(sc[nb][0], sc[nb][1]));
                tm1 = fmaxf(tm1, fmaxf(sc[nb][2], sc[nb][3]));
            }
        }
        tm0 = fmaxf(tm0, __shfl_xor_sync(0xffffffffu, tm0, 1));
        tm0 = fmaxf(tm0, __shfl_xor_sync(0xffffffffu, tm0, 2));
        tm1 = fmaxf(tm1, __shfl_xor_sync(0xffffffffu, tm1, 1));
        tm1 = fmaxf(tm1, __shfl_xor_sync(0xffffffffu, tm1, 2));

        const float nm0 = fmaxf(m0, tm0);
        const float nm1 = fmaxf(m1, tm1);
        const float c0 = fexp2(m0 - nm0);
        const float c1 = fexp2(m1 - nm1);
        l0 *= c0; l1 *= c1;
        #pragma unroll
        for (int nb = 0; nb < 8; nb++) {
            O[nb][0] *= c0; O[nb][1] *= c0;
            O[nb][2] *= c1; O[nb][3] *= c1;
        }
        m0 = nm0; m1 = nm1;

        #pragma unroll
        for (int nb = 0; nb < 8; nb++) {
            float p0 = fexp2(sc[nb][0] - m0);
            float p1 = fexp2(sc[nb][1] - m0);
            float p2 = fexp2(sc[nb][2] - m1);
            float p3 = fexp2(sc[nb][3] - m1);
            l0 += p0 + p1;
            l1 += p2 + p3;
            uint2 u0 = { f2tf32(p0), f2tf32(p1) };
            uint2 u1 = { f2tf32(p2), f2tf32(p3) };
            *(uint2*)(Pw + (g    ) * PS_STRIDE + nb * 8 + 2 * t) = u0;
            *(uint2*)(Pw + (g + 8) * PS_STRIDE + nb * 8 + 2 * t) = u1;
        }
        __syncwarp();

        // O += P @ V
        #pragma unroll
        for (int ks = 0; ks < 8; ks++) {
            uint32_t pa[4];
            pa[0] = __float_as_uint(Pw[(g    ) * PS_STRIDE + ks * 8 + t    ]);
            pa[1] = __float_as_uint(Pw[(g + 8) * PS_STRIDE + ks * 8 + t    ]);
            pa[2] = __float_as_uint(Pw[(g    ) * PS_STRIDE + ks * 8 + t + 4]);
            pa[3] = __float_as_uint(Pw[(g + 8) * PS_STRIDE + ks * 8 + t + 4]);
            #pragma unroll
            for (int nb = 0; nb < 8; nb++) {
                uint32_t bf[2];
                bf[0] = __float_as_uint(Vsm[(ks * 8 + t    ) * VS_STRIDE + nb * 8 + g]);
                bf[1] = __float_as_uint(Vsm[(ks * 8 + t + 4) * VS_STRIDE + nb * 8 + g]);
                mma_tf32(O[nb], pa, bf);
            }
        }
        __syncthreads();                       // buffer ti&1 fully consumed
        if (ti + 2 < ntiles) load_kv(ti & 1, (ti + 2) * AK);
    }

    l0 += __shfl_xor_sync(0xffffffffu, l0, 1);
    l0 += __shfl_xor_sync(0xffffffffu, l0, 2);
    l1 += __shfl_xor_sync(0xffffffffu, l1, 1);
    l1 += __shfl_xor_sync(0xffffffffu, l1, 2);
    const float inv0 = 1.f / l0;
    const float inv1 = 1.f / l1;

    float* out0 = out + (size_t)(b * SEQ + rg    ) * CDIM + h * HDIM;
    float* out8 = out + (size_t)(b * SEQ + rg + 8) * CDIM + h * HDIM;
    #pragma unroll
    for (int nb = 0; nb < 8; nb++) {
        float2 v0, v1;
        v0.x = __uint_as_float(f2tf32(O[nb][0] * inv0));
        v0.y = __uint_as_float(f2tf32(O[nb][1] * inv0));
        v1.x = __uint_as_float(f2tf32(O[nb][2] * inv1));
        v1.y = __uint_as_float(f2tf32(O[nb][3] * inv1));
        *(float2*)(out0 + nb * 8 + 2 * t) = v0;
        *(float2*)(out8 + nb * 8 + 2 * t) = v1;
    }
}

// ---------------------------------------------------------------------------
// Launch
// ---------------------------------------------------------------------------
extern "C" void kernel_launch(void* const* d_in, const int* in_sizes, int n_in,
                              void* d_out, int out_size)
{
    const float* x    = (const float*)d_in[0];
    const float* Wqkv = (const float*)d_in[1];
    const float* bqkv = (const float*)d_in[2];
    const float* Wout = (const float*)d_in[3];
    const float* bout = (const float*)d_in[4];
    float* out = (float*)d_out;

    float *qkv, *attn, *xr, *wqkvr, *woutr;
    cudaGetSymbolAddress((void**)&qkv,   g_qkv);
    cudaGetSymbolAddress((void**)&attn,  g_attn);
    cudaGetSymbolAddress((void**)&xr,    g_xr);
    cudaGetSymbolAddress((void**)&wqkvr, g_wqkvr);
    cudaGetSymbolAddress((void**)&woutr, g_woutr);

    static bool attr_set = false;
    if (!attr_set) {
        cudaFuncSetAttribute(gemm_tc_kernel<true>,  cudaFuncAttributeMaxDynamicSharedMemorySize, GEMM_SMEM);
        cudaFuncSetAttribute(gemm_tc_kernel<false>, cudaFuncAttributeMaxDynamicSharedMemorySize, GEMM_SMEM);
        cudaFuncSetAttribute(attn_tc_kernel, cudaFuncAttributeMaxDynamicSharedMemorySize, ATTN_SMEM);
        attr_set = true;
    }

    // 0) Pre-round GEMM operands to tf32 (single fused launch)
    round3_kernel<<<(RNT + 255) / 256, 256>>>(x, xr, Wqkv, wqkvr, Wout, woutr);

    // 1) QKV projection (rounds outputs -> attention operands pre-rounded)
    {
        dim3 grid(C3 / GBN, MROWS / GBM);
        gemm_tc_kernel<true><<<grid, 256, GEMM_SMEM>>>(xr, wqkvr, bqkv, qkv, MROWS, C3, CDIM);
    }
    // 2) Causal flash attention (tensor cores) -> g_attn (tf32-rounded)
    {
        dim3 grid(SEQ / AQ, NHEAD, BATCH);
        attn_tc_kernel<<<grid, 256, ATTN_SMEM>>>(qkv, attn);
    }
    // 3) Output projection (fp32 output)
    {
        dim3 grid(CDIM / GBN, MROWS / GBM);
        gemm_tc_kernel<false><<<grid, 256, GEMM_SMEM>>>(attn, woutr, bout, out, MROWS, CDIM, CDIM);
    }
}

// round 11
// speedup vs baseline: 1.9876x; 1.7451x over previous
#include <cuda_runtime.h>
#include <cuda_fp16.h>
#include <math.h>
#include <stdint.h>

// Problem constants
#define BATCH 2
#define SEQ   2048
#define CDIM  1024
#define NHEAD 16
#define HDIM  64
#define C3    (3*CDIM)          // 3072
#define MROWS (BATCH*SEQ)       // 4096

// Scratch (no cudaMalloc allowed)
__device__ __half g_qkvh[(size_t)MROWS * C3];      // [B,T,3,H,D] fp16
__device__ __half g_vT[(size_t)BATCH * NHEAD * HDIM * SEQ]; // V transposed [b][h][d][t]
__device__ __half g_attnh[(size_t)MROWS * CDIM];   // attention out fp16
__device__ __half g_xh[(size_t)MROWS * CDIM];      // x fp16
__device__ __half g_wqkvT[(size_t)C3 * CDIM];      // Wqkv^T [3072][1024] fp16
__device__ __half g_woutT[(size_t)CDIM * CDIM];    // Wout^T fp16

__device__ __forceinline__ float fexp2(float x) {
    float y;
    asm("ex2.approx.f32 %0, %1;" : "=f"(y) : "f"(x));
    return y;
}
__device__ __forceinline__ uint32_t smem_u32(const void* p) {
    uint32_t a;
    asm("{ .reg .u64 t; cvta.to.shared.u64 t, %1; cvt.u32.u64 %0, t; }" : "=r"(a) : "l"(p));
    return a;
}
__device__ __forceinline__ uint32_t pack_h2(float a, float b) {
    __half2 h = __floats2half2_rn(a, b);
    return *(uint32_t*)&h;
}
#define CP_ASYNC16(dst_u32, src_ptr) \
    asm volatile("cp.async.cg.shared.global [%0], [%1], 16;" :: "r"(dst_u32), "l"(src_ptr) : "memory")
#define CP_COMMIT() asm volatile("cp.async.commit_group;" ::: "memory")
#define CP_WAIT0()  asm volatile("cp.async.wait_group 0;" ::: "memory")
#define CP_WAIT1()  asm volatile("cp.async.wait_group 1;" ::: "memory")

// m16n8k16 fp16 mma, fp32 accumulate
__device__ __forceinline__ void mma_f16(float c[4], const uint32_t a[4], const uint32_t b[2]) {
    asm volatile(
        "mma.sync.aligned.m16n8k16.row.col.f32.f16.f16.f32 "
        "{%0,%1,%2,%3}, {%4,%5,%6,%7}, {%8,%9}, {%0,%1,%2,%3};"
        : "+f"(c[0]), "+f"(c[1]), "+f"(c[2]), "+f"(c[3])
        : "r"(a[0]), "r"(a[1]), "r"(a[2]), "r"(a[3]), "r"(b[0]), "r"(b[1]));
}

// ---------------------------------------------------------------------------
// Pre-pass: x -> fp16
// ---------------------------------------------------------------------------
__global__ __launch_bounds__(256)
void xconv_kernel(const float* __restrict__ in, __half* __restrict__ out, int n8)
{
    int i = blockIdx.x * blockDim.x + threadIdx.x;
    if (i >= n8) return;
    float4 v0 = ((const float4*)in)[2 * i];
    float4 v1 = ((const float4*)in)[2 * i + 1];
    uint4 o;
    o.x = pack_h2(v0.x, v0.y);
    o.y = pack_h2(v0.z, v0.w);
    o.z = pack_h2(v1.x, v1.y);
    o.w = pack_h2(v1.z, v1.w);
    ((uint4*)out)[i] = o;
}

// ---------------------------------------------------------------------------
// Pre-pass: weight transpose+convert: out[n][k] = fp16(in[k][n])
// ---------------------------------------------------------------------------
__global__ __launch_bounds__(256)
void wtrans_kernel(const float* __restrict__ in, __half* __restrict__ out, int K, int N)
{
    __shared__ float tile[32][33];
    const int k0 = blockIdx.y * 32;
    const int n0 = blockIdx.x * 32;
    const int tx = threadIdx.x & 31;
    const int ty = threadIdx.x >> 5;   // 0..7
    #pragma unroll
    for (int i = 0; i < 32; i += 8)
        tile[ty + i][tx] = in[(size_t)(k0 + ty + i) * N + n0 + tx];
    __syncthreads();
    #pragma unroll
    for (int i = 0; i < 32; i += 8)
        out[(size_t)(n0 + ty + i) * K + k0 + tx] = __float2half_rn(tile[tx][ty + i]);
}

// ---------------------------------------------------------------------------
// V transpose: g_vT[b][h][d][t] = g_qkvh V-part (b,t,h,d)
// ---------------------------------------------------------------------------
__global__ __launch_bounds__(256)
void vtrans_kernel(const __half* __restrict__ qkvh, __half* __restrict__ vT)
{
    __shared__ __half tile[64][68];
    const int tb = blockIdx.x * 64;
    const int bh = blockIdx.y;
    const int b  = bh >> 4;
    const int h  = bh & 15;
    const int tid = threadIdx.x;
    const int rr = tid >> 4;         // 0..15
    const int c4 = (tid & 15) * 4;   // 0..60
    #pragma unroll
    for (int it = 0; it < 4; it++) {
        const int tt = it * 16 + rr;
        const __half* src = qkvh + (size_t)(b * SEQ + tb + tt) * C3 + 2 * CDIM + h * HDIM + c4;
        uint2 v = *(const uint2*)src;
        *(uint2*)&tile[tt][c4] = v;
    }
    __syncthreads();
    #pragma unroll
    for (int it = 0; it < 4; it++) {
        const int d = it * 16 + rr;
        __half vals[4];
        #pragma unroll
        for (int q = 0; q < 4; q++) vals[q] = tile[c4 + q][d];
        __half* dst = vT + ((size_t)(b * NHEAD + h) * HDIM + d) * SEQ + tb + c4;
        *(uint2*)dst = *(uint2*)vals;
    }
}

// ---------------------------------------------------------------------------
// fp16 mma GEMM + bias: C[M,N] = A[M,K] @ Bt[N,K]^T + bias[N]
// A [M][K] fp16, Bt [N][K] fp16. CTA 128x128, BK=64, 8 warps (2x4),
// warp tile 64x32. cp.async 3-stage, one barrier per chunk.
// RND=true: C is __half (intermediate); else float (final).
// ---------------------------------------------------------------------------
#define GBM 128
#define GBN 128
#define GBK 64
#define T_STRIDE 72                       // halves per row (64 + 8 pad)
#define TILE_HALVES (128 * T_STRIDE)      // 9216
#define STG_HALVES (2 * TILE_HALVES)      // 18432
#define GEMM_SMEM (3 * STG_HALVES * 2)    // 110592 B

template<bool RND>
__global__ __launch_bounds__(256)
void gemm_h_kernel(const __half* __restrict__ A,
                   const __half* __restrict__ Bt,
                   const float* __restrict__ bias,
                   void* __restrict__ Cv,
                   int M, int N, int K)
{
    extern __shared__ char smem_raw[];
    __half* smem = (__half*)smem_raw;
    const int tid = threadIdx.x;
    const int wid = tid >> 5;
    const int l   = tid & 31;
    const int warpM = wid >> 2;
    const int warpN = wid & 3;
    const int g = l >> 2;
    const int t = l & 3;
    const int rowbase = blockIdx.y * GBM;
    const int colbase = blockIdx.x * GBN;

    const uint32_t smb = smem_u32(smem);

    float acc[4][4][4];
    #pragma unroll
    for (int i = 0; i < 4; i++)
        #pragma unroll
        for (int j = 0; j < 4; j++)
            #pragma unroll
            for (int q = 0; q < 4; q++) acc[i][j][q] = 0.f;

    const int S = K / GBK;

    // loader: idx = it*256+tid -> r = idx/8 (0..127), c8 = (idx%8)*8 halves
    auto load_stage = [&](int stg, int k0) {
        const uint32_t sa = smb + (uint32_t)(stg * STG_HALVES) * 2;
        const uint32_t sb = sa + (uint32_t)TILE_HALVES * 2;
        #pragma unroll
        for (int it = 0; it < 4; it++) {
            const int idx = it * 256 + tid;
            const int r  = idx >> 3;
            const int c8 = (idx & 7) * 8;
            CP_ASYNC16(sa + (uint32_t)(r * T_STRIDE + c8) * 2,
                       A + (size_t)(rowbase + r) * K + k0 + c8);
            CP_ASYNC16(sb + (uint32_t)(r * T_STRIDE + c8) * 2,
                       Bt + (size_t)(colbase + r) * K + k0 + c8);
        }
        CP_COMMIT();
    };

    load_stage(0, 0);
    load_stage(1, GBK);

    const int arow0 = warpM * 64 + g;
    const int bcol0 = warpN * 32 + g;

    for (int s = 0; s < S; s++) {
        if (s + 1 < S) { CP_WAIT1(); } else { CP_WAIT0(); }
        __syncthreads();
        if (s + 2 < S) load_stage((s + 2) % 3, (s + 2) * GBK);

        const __half* as = smem + (s % 3) * STG_HALVES;
        const __half* bs = as + TILE_HALVES;
        #pragma unroll
        for (int ks = 0; ks < 4; ks++) {
            const int kk = ks * 16 + 2 * t;     // half index of pair start
            uint32_t af[4][4], bf[4][2];
            #pragma unroll
            for (int i = 0; i < 4; i++) {
                const int r = arow0 + i * 16;
                af[i][0] = *(const uint32_t*)(as + (r    ) * T_STRIDE + kk);
                af[i][1] = *(const uint32_t*)(as + (r + 8) * T_STRIDE + kk);
                af[i][2] = *(const uint32_t*)(as + (r    ) * T_STRIDE + kk + 8);
                af[i][3] = *(const uint32_t*)(as + (r + 8) * T_STRIDE + kk + 8);
            }
            #pragma unroll
            for (int j = 0; j < 4; j++) {
                const int n = bcol0 + j * 8;
                bf[j][0] = *(const uint32_t*)(bs + n * T_STRIDE + kk);
                bf[j][1] = *(const uint32_t*)(bs + n * T_STRIDE + kk + 8);
            }
            #pragma unroll
            for (int i = 0; i < 4; i++)
                #pragma unroll
                for (int j = 0; j < 4; j++)
                    mma_f16(acc[i][j], af[i], bf[j]);
        }
    }

    const int erow = rowbase + warpM * 64 + g;
    const int ecol = colbase + warpN * 32 + 2 * t;
    #pragma unroll
    for (int i = 0; i < 4; i++) {
        #pragma unroll
        for (int j = 0; j < 4; j++) {
            const int r0 = erow + i * 16;
            const int c0 = ecol + j * 8;
            const float b0 = bias[c0], b1 = bias[c0 + 1];
            if (RND) {
                __half* C = (__half*)Cv;
                *(uint32_t*)(C + (size_t)r0 * N + c0)       = pack_h2(acc[i][j][0] + b0, acc[i][j][1] + b1);
                *(uint32_t*)(C + (size_t)(r0 + 8) * N + c0) = pack_h2(acc[i][j][2] + b0, acc[i][j][3] + b1);
            } else {
                float* C = (float*)Cv;
                float2 v0 = { acc[i][j][0] + b0, acc[i][j][1] + b1 };
                float2 v1 = { acc[i][j][2] + b0, acc[i][j][3] + b1 };
                *(float2*)(C + (size_t)r0 * N + c0)       = v0;
                *(float2*)(C + (size_t)(r0 + 8) * N + c0) = v1;
            }
        }
    }
}

// ---------------------------------------------------------------------------
// fp16 tensor-core flash attention. Q,K from g_qkvh [t][...]; V from g_vT
// [b][h][d][t]. cp.async double-buffered K/V; P staged per-warp in fp16.
// CTA = 128 q rows of one (b,h); 8 warps x 16 rows. K-tile = 64 keys.
// ---------------------------------------------------------------------------
#define AQ 128
#define AK 64
#define HS 72                              // padded stride (halves)
#define K_HALVES (AK * HS)                 // 4608
#define V_HALVES (HDIM * HS)               // 4608
#define KV_HALVES (K_HALVES + V_HALVES)    // 9216 per stage
#define P_HALVES (8 * 16 * HS)             // 9216
#define ATTN_SMEM ((2 * KV_HALVES + P_HALVES) * 2)   // 55296 B

__global__ __launch_bounds__(256)
void attn_h_kernel(const __half* __restrict__ qkv, const __half* __restrict__ vT,
                   __half* __restrict__ out)
{
    extern __shared__ char smem_raw[];
    __half* sm = (__half*)smem_raw;
    __half* Psm = sm + 2 * KV_HALVES;

    const int qtile = gridDim.x - 1 - blockIdx.x;   // heavy tiles first
    const int h   = blockIdx.y;
    const int b   = blockIdx.z;
    const int tid = threadIdx.x;
    const int wid = tid >> 5;
    const int l   = tid & 31;
    const int g   = l >> 2;
    const int t   = l & 3;
    const int qb  = qtile * AQ;
    const int rg  = qb + wid * 16 + g;

    const float SC = 0.18033688011112042f;   // (1/sqrt(64)) * log2(e)
    __half* Pw = Psm + wid * (16 * HS);
    const uint32_t smb = smem_u32(sm);

    auto load_kv = [&](int stg, int kb) {
        const uint32_t kbuf = smb + (uint32_t)(stg * KV_HALVES) * 2;
        const uint32_t vbuf = kbuf + (uint32_t)K_HALVES * 2;
        #pragma unroll
        for (int it = 0; it < 2; it++) {
            const int idx = it * 256 + tid;
            const int r  = idx >> 3;           // 0..63
            const int c8 = (idx & 7) * 8;      // 0..56
            // K rows: key kb+r, dims c8..c8+7
            CP_ASYNC16(kbuf + (uint32_t)(r * HS + c8) * 2,
                       qkv + (size_t)(b * SEQ + kb + r) * C3 + CDIM + h * HDIM + c8);
            // V rows: dim r, keys kb+c8..
            CP_ASYNC16(vbuf + (uint32_t)(r * HS + c8) * 2,
                       vT + ((size_t)(b * NHEAD + h) * HDIM + r) * SEQ + kb + c8);
        }
        CP_COMMIT();
    };

    // Q fragments (fp16 pairs), softmax scale folded
    uint32_t qa[4][4];
    {
        const __half* Qr  = qkv + (size_t)(b * SEQ + rg    ) * C3 + h * HDIM;
        const __half* Qr8 = qkv + (size_t)(b * SEQ + rg + 8) * C3 + h * HDIM;
        #pragma unroll
        for (int ks = 0; ks < 4; ks++) {
            #pragma unroll
            for (int q = 0; q < 4; q++) {
                const __half* src = (q & 1) ? Qr8 : Qr;
                const int off = ks * 16 + 2 * t + ((q >> 1) ? 8 : 0);
                __half2 hv = *(const __half2*)(src + off);
                float2 fv = __half22float2(hv);
                qa[ks][q] = pack_h2(fv.x * SC, fv.y * SC);
            }
        }
    }

    float O[8][4];
    #pragma unroll
    for (int nb = 0; nb < 8; nb++)
        #pragma unroll
        for (int q = 0; q < 4; q++) O[nb][q] = 0.f;
    float m0 = -INFINITY, m1 = -INFINITY, l0 = 0.f, l1 = 0.f;

    const int ntiles = (qb + AQ) / AK;

    load_kv(0, 0);
    if (ntiles > 1) load_kv(1, AK);

    for (int ti = 0; ti < ntiles; ti++) {
        if (ti + 1 < ntiles) { CP_WAIT1(); } else { CP_WAIT0(); }
        __syncthreads();

        const __half* Ksm = sm + (ti & 1) * KV_HALVES;
        const __half* Vsm = Ksm + K_HALVES;
        const int kb = ti * AK;

        // S = Q @ K^T (scaled, log2 domain)
        float sc[8][4];
        #pragma unroll
        for (int nb = 0; nb < 8; nb++) {
            sc[nb][0] = 0.f; sc[nb][1] = 0.f; sc[nb][2] = 0.f; sc[nb][3] = 0.f;
        }
        #pragma unroll
        for (int ks = 0; ks < 4; ks++) {
            const int kk = ks * 16 + 2 * t;
            #pragma unroll
            for (int nb = 0; nb < 8; nb++) {
                uint32_t bf[2];
                bf[0] = *(const uint32_t*)(Ksm + (nb * 8 + g) * HS + kk);
                bf[1] = *(const uint32_t*)(Ksm + (nb * 8 + g) * HS + kk + 8);
                mma_f16(sc[nb], qa[ks], bf);
            }
        }

        const bool needmask = (kb + AK - 1) > (qb + wid * 16);
        float tm0 = -INFINITY, tm1 = -INFINITY;
        if (needmask) {
            #pragma unroll
            for (int nb = 0; nb < 8; nb++) {
                const int k0 = kb + nb * 8 + 2 * t;
                if (k0     > rg    ) sc[nb][0] = -INFINITY;
                if (k0 + 1 > rg    ) sc[nb][1] = -INFINITY;
                if (k0     > rg + 8) sc[nb][2] = -INFINITY;
                if (k0 + 1 > rg + 8) sc[nb][3] = -INFINITY;
                tm0 = fmaxf(tm0, fmaxf(sc[nb][0], sc[nb][1]));
                tm1 = fmaxf(tm1, fmaxf(sc[nb][2], sc[nb][3]));
            }
        } else {
            #pragma unroll
            for (int nb = 0; nb < 8; nb++) {
                tm0 = fmaxf(tm0, fmaxf(sc[nb][0], sc[nb][1]));
                tm1 = fmaxf(tm1, fmaxf(sc[nb][2], sc[nb][3]));
            }
        }
        tm0 = fmaxf(tm0, __shfl_xor_sync(0xffffffffu, tm0, 1));
        tm0 = fmaxf(tm0, __shfl_xor_sync(0xffffffffu, tm0, 2));
        tm1 = fmaxf(tm1, __shfl_xor_sync(0xffffffffu, tm1, 1));
        tm1 = fmaxf(tm1, __shfl_xor_sync(0xffffffffu, tm1, 2));

        const float nm0 = fmaxf(m0, tm0);
        const float nm1 = fmaxf(m1, tm1);
        const float c0 = fexp2(m0 - nm0);
        const float c1 = fexp2(m1 - nm1);
        l0 *= c0; l1 *= c1;
        #pragma unroll
        for (int nb = 0; nb < 8; nb++) {
            O[nb][0] *= c0; O[nb][1] *= c0;
            O[nb][2] *= c1; O[nb][3] *= c1;
        }
        m0 = nm0; m1 = nm1;

        #pragma unroll
        for (int nb = 0; nb < 8; nb++) {
            float p0 = fexp2(sc[nb][0] - m0);
            float p1 = fexp2(sc[nb][1] - m0);
            float p2 = fexp2(sc[nb][2] - m1);
            float p3 = fexp2(sc[nb][3] - m1);
            l0 += p0 + p1;
            l1 += p2 + p3;
            *(uint32_t*)(Pw + (g    ) * HS + nb * 8 + 2 * t) = pack_h2(p0, p1);
            *(uint32_t*)(Pw + (g + 8) * HS + nb * 8 + 2 * t) = pack_h2(p2, p3);
        }
        __syncwarp();

        // O += P @ V  (V in [d][key] layout)
        #pragma unroll
        for (int ks = 0; ks < 4; ks++) {
            const int kk = ks * 16 + 2 * t;
            uint32_t pa[4];
            pa[0] = *(const uint32_t*)(Pw + (g    ) * HS + kk);
            pa[1] = *(const uint32_t*)(Pw + (g + 8) * HS + kk);
            pa[2] = *(const uint32_t*)(Pw + (g    ) * HS + kk + 8);
            pa[3] = *(const uint32_t*)(Pw + (g + 8) * HS + kk + 8);
            #pragma unroll
            for (int nb = 0; nb < 8; nb++) {
                uint32_t bf[2];
                bf[0] = *(const uint32_t*)(Vsm + (nb * 8 + g) * HS + kk);
                bf[1] = *(const uint32_t*)(Vsm + (nb * 8 + g) * HS + kk + 8);
                mma_f16(O[nb], pa, bf);
            }
        }
        __syncthreads();                      // buffer fully consumed
        if (ti + 2 < ntiles) load_kv(ti & 1, (ti + 2) * AK);
    }

    l0 += __shfl_xor_sync(0xffffffffu, l0, 1);
    l0 += __shfl_xor_sync(0xffffffffu, l0, 2);
    l1 += __shfl_xor_sync(0xffffffffu, l1, 1);
    l1 += __shfl_xor_sync(0xffffffffu, l1, 2);
    const float inv0 = 1.f / l0;
    const float inv1 = 1.f / l1;

    __half* out0 = out + (size_t)(b * SEQ + rg    ) * CDIM + h * HDIM;
    __half* out8 = out + (size_t)(b * SEQ + rg + 8) * CDIM + h * HDIM;
    #pragma unroll
    for (int nb = 0; nb < 8; nb++) {
        *(uint32_t*)(out0 + nb * 8 + 2 * t) = pack_h2(O[nb][0] * inv0, O[nb][1] * inv0);
        *(uint32_t*)(out8 + nb * 8 + 2 * t) = pack_h2(O[nb][2] * inv1, O[nb][3] * inv1);
    }
}

// ---------------------------------------------------------------------------
// Launch
// ---------------------------------------------------------------------------
extern "C" void kernel_launch(void* const* d_in, const int* in_sizes, int n_in,
                              void* d_out, int out_size)
{
    const float* x    = (const float*)d_in[0];
    const float* Wqkv = (const float*)d_in[1];
    const float* bqkv = (const float*)d_in[2];
    const float* Wout = (const float*)d_in[3];
    const float* bout = (const float*)d_in[4];
    float* out = (float*)d_out;

    __half *qkvh, *vT, *attnh, *xh, *wqkvT, *woutT;
    cudaGetSymbolAddress((void**)&qkvh,  g_qkvh);
    cudaGetSymbolAddress((void**)&vT,    g_vT);
    cudaGetSymbolAddress((void**)&attnh, g_attnh);
    cudaGetSymbolAddress((void**)&xh,    g_xh);
    cudaGetSymbolAddress((void**)&wqkvT, g_wqkvT);
    cudaGetSymbolAddress((void**)&woutT, g_woutT);

    static bool attr_set = false;
    if (!attr_set) {
        cudaFuncSetAttribute(gemm_h_kernel<true>,  cudaFuncAttributeMaxDynamicSharedMemorySize, GEMM_SMEM);
        cudaFuncSetAttribute(gemm_h_kernel<false>, cudaFuncAttributeMaxDynamicSharedMemorySize, GEMM_SMEM);
        cudaFuncSetAttribute(attn_h_kernel, cudaFuncAttributeMaxDynamicSharedMemorySize, ATTN_SMEM);
        attr_set = true;
    }

    // 0) Pre-pass: x -> fp16; weights -> fp16 transposed [N][K]
    xconv_kernel<<<(MROWS * CDIM / 8 + 255) / 256, 256>>>(x, xh, MROWS * CDIM / 8);
    {
        dim3 grid(C3 / 32, CDIM / 32);
        wtrans_kernel<<<grid, 256>>>(Wqkv, wqkvT, CDIM, C3);
    }
    {
        dim3 grid(CDIM / 32, CDIM / 32);
        wtrans_kernel<<<grid, 256>>>(Wout, woutT, CDIM, CDIM);
    }

    // 1) QKV projection -> fp16
    {
        dim3 grid(C3 / GBN, MROWS / GBM);
        gemm_h_kernel<true><<<grid, 256, GEMM_SMEM>>>(xh, wqkvT, bqkv, qkvh, MROWS, C3, CDIM);
    }
    // 1b) V transpose -> [b][h][d][t]
    {
        dim3 grid(SEQ / 64, BATCH * NHEAD);
        vtrans_kernel<<<grid, 256>>>(qkvh, vT);
    }
    // 2) Causal flash attention -> fp16
    {
        dim3 grid(SEQ / AQ, NHEAD, BATCH);
        attn_h_kernel<<<grid, 256, ATTN_SMEM>>>(qkvh, vT, attnh);
    }
    // 3) Output projection -> fp32
    {
        dim3 grid(CDIM / GBN, MROWS / GBM);
        gemm_h_kernel<false><<<grid, 256, GEMM_SMEM>>>(attnh, woutT, bout, out, MROWS, CDIM, CDIM);
    }
}

// round 12
// speedup vs baseline: 2.1167x; 1.0649x over previous
#include <cuda_runtime.h>
#include <cuda_fp16.h>
#include <math.h>
#include <stdint.h>

// Problem constants
#define BATCH 2
#define SEQ   2048
#define CDIM  1024
#define NHEAD 16
#define HDIM  64
#define C3    (3*CDIM)          // 3072
#define MROWS (BATCH*SEQ)       // 4096

// Scratch (no cudaMalloc allowed)
__device__ __half g_qkvh[(size_t)MROWS * C3];      // [B,T,3,H,D] fp16
__device__ __half g_vT[(size_t)BATCH * NHEAD * HDIM * SEQ]; // V transposed [b][h][d][t]
__device__ __half g_attnh[(size_t)MROWS * CDIM];   // attention out fp16
__device__ __half g_xh[(size_t)MROWS * CDIM];      // x fp16
__device__ __half g_wqkvT[(size_t)C3 * CDIM];      // Wqkv^T [3072][1024] fp16
__device__ __half g_woutT[(size_t)CDIM * CDIM];    // Wout^T fp16

__device__ __forceinline__ float fexp2(float x) {
    float y;
    asm("ex2.approx.f32 %0, %1;" : "=f"(y) : "f"(x));
    return y;
}
__device__ __forceinline__ uint32_t smem_u32(const void* p) {
    uint32_t a;
    asm("{ .reg .u64 t; cvta.to.shared.u64 t, %1; cvt.u32.u64 %0, t; }" : "=r"(a) : "l"(p));
    return a;
}
__device__ __forceinline__ uint32_t pack_h2(float a, float b) {
    __half2 h = __floats2half2_rn(a, b);
    return *(uint32_t*)&h;
}
#define CP_ASYNC16(dst_u32, src_ptr) \
    asm volatile("cp.async.cg.shared.global [%0], [%1], 16;" :: "r"(dst_u32), "l"(src_ptr) : "memory")
#define CP_COMMIT() asm volatile("cp.async.commit_group;" ::: "memory")
#define CP_WAIT0()  asm volatile("cp.async.wait_group 0;" ::: "memory")
#define CP_WAIT1()  asm volatile("cp.async.wait_group 1;" ::: "memory")

// m16n8k16 fp16 mma, fp32 accumulate
__device__ __forceinline__ void mma_f16(float c[4], const uint32_t a[4], const uint32_t b[2]) {
    asm volatile(
        "mma.sync.aligned.m16n8k16.row.col.f32.f16.f16.f32 "
        "{%0,%1,%2,%3}, {%4,%5,%6,%7}, {%8,%9}, {%0,%1,%2,%3};"
        : "+f"(c[0]), "+f"(c[1]), "+f"(c[2]), "+f"(c[3])
        : "r"(a[0]), "r"(a[1]), "r"(a[2]), "r"(a[3]), "r"(b[0]), "r"(b[1]));
}

// ---------------------------------------------------------------------------
// Pre-pass: x -> fp16
// ---------------------------------------------------------------------------
__global__ __launch_bounds__(256)
void xconv_kernel(const float* __restrict__ in, __half* __restrict__ out, int n8)
{
    int i = blockIdx.x * blockDim.x + threadIdx.x;
    if (i >= n8) return;
    float4 v0 = ((const float4*)in)[2 * i];
    float4 v1 = ((const float4*)in)[2 * i + 1];
    uint4 o;
    o.x = pack_h2(v0.x, v0.y);
    o.y = pack_h2(v0.z, v0.w);
    o.z = pack_h2(v1.x, v1.y);
    o.w = pack_h2(v1.z, v1.w);
    ((uint4*)out)[i] = o;
}

// ---------------------------------------------------------------------------
// Pre-pass: weight transpose+convert: out[n][k] = fp16(in[k][n])
// ---------------------------------------------------------------------------
__global__ __launch_bounds__(256)
void wtrans_kernel(const float* __restrict__ in, __half* __restrict__ out, int K, int N)
{
    __shared__ float tile[32][33];
    const int k0 = blockIdx.y * 32;
    const int n0 = blockIdx.x * 32;
    const int tx = threadIdx.x & 31;
    const int ty = threadIdx.x >> 5;   // 0..7
    #pragma unroll
    for (int i = 0; i < 32; i += 8)
        tile[ty + i][tx] = in[(size_t)(k0 + ty + i) * N + n0 + tx];
    __syncthreads();
    #pragma unroll
    for (int i = 0; i < 32; i += 8)
        out[(size_t)(n0 + ty + i) * K + k0 + tx] = __float2half_rn(tile[tx][ty + i]);
}

// ---------------------------------------------------------------------------
// V transpose: g_vT[b][h][d][t] = g_qkvh V-part (b,t,h,d)
// ---------------------------------------------------------------------------
__global__ __launch_bounds__(256)
void vtrans_kernel(const __half* __restrict__ qkvh, __half* __restrict__ vT)
{
    __shared__ __half tile[64][68];
    const int tb = blockIdx.x * 64;
    const int bh = blockIdx.y;
    const int b  = bh >> 4;
    const int h  = bh & 15;
    const int tid = threadIdx.x;
    const int rr = tid >> 4;         // 0..15
    const int c4 = (tid & 15) * 4;   // 0..60
    #pragma unroll
    for (int it = 0; it < 4; it++) {
        const int tt = it * 16 + rr;
        const __half* src = qkvh + (size_t)(b * SEQ + tb + tt) * C3 + 2 * CDIM + h * HDIM + c4;
        uint2 v = *(const uint2*)src;
        *(uint2*)&tile[tt][c4] = v;
    }
    __syncthreads();
    #pragma unroll
    for (int it = 0; it < 4; it++) {
        const int d = it * 16 + rr;
        __half vals[4];
        #pragma unroll
        for (int q = 0; q < 4; q++) vals[q] = tile[c4 + q][d];
        __half* dst = vT + ((size_t)(b * NHEAD + h) * HDIM + d) * SEQ + tb + c4;
        *(uint2*)dst = *(uint2*)vals;
    }
}

// ---------------------------------------------------------------------------
// fp16 mma GEMM + bias (unchanged from R11): C = A @ Bt^T + bias
// ---------------------------------------------------------------------------
#define GBM 128
#define GBN 128
#define GBK 64
#define T_STRIDE 72
#define TILE_HALVES (128 * T_STRIDE)
#define STG_HALVES (2 * TILE_HALVES)
#define GEMM_SMEM (3 * STG_HALVES * 2)

template<bool RND>
__global__ __launch_bounds__(256)
void gemm_h_kernel(const __half* __restrict__ A,
                   const __half* __restrict__ Bt,
                   const float* __restrict__ bias,
                   void* __restrict__ Cv,
                   int M, int N, int K)
{
    extern __shared__ char smem_raw[];
    __half* smem = (__half*)smem_raw;
    const int tid = threadIdx.x;
    const int wid = tid >> 5;
    const int l   = tid & 31;
    const int warpM = wid >> 2;
    const int warpN = wid & 3;
    const int g = l >> 2;
    const int t = l & 3;
    const int rowbase = blockIdx.y * GBM;
    const int colbase = blockIdx.x * GBN;

    const uint32_t smb = smem_u32(smem);

    float acc[4][4][4];
    #pragma unroll
    for (int i = 0; i < 4; i++)
        #pragma unroll
        for (int j = 0; j < 4; j++)
            #pragma unroll
            for (int q = 0; q < 4; q++) acc[i][j][q] = 0.f;

    const int S = K / GBK;

    auto load_stage = [&](int stg, int k0) {
        const uint32_t sa = smb + (uint32_t)(stg * STG_HALVES) * 2;
        const uint32_t sb = sa + (uint32_t)TILE_HALVES * 2;
        #pragma unroll
        for (int it = 0; it < 4; it++) {
            const int idx = it * 256 + tid;
            const int r  = idx >> 3;
            const int c8 = (idx & 7) * 8;
            CP_ASYNC16(sa + (uint32_t)(r * T_STRIDE + c8) * 2,
                       A + (size_t)(rowbase + r) * K + k0 + c8);
            CP_ASYNC16(sb + (uint32_t)(r * T_STRIDE + c8) * 2,
                       Bt + (size_t)(colbase + r) * K + k0 + c8);
        }
        CP_COMMIT();
    };

    load_stage(0, 0);
    load_stage(1, GBK);

    const int arow0 = warpM * 64 + g;
    const int bcol0 = warpN * 32 + g;

    for (int s = 0; s < S; s++) {
        if (s + 1 < S) { CP_WAIT1(); } else { CP_WAIT0(); }
        __syncthreads();
        if (s + 2 < S) load_stage((s + 2) % 3, (s + 2) * GBK);

        const __half* as = smem + (s % 3) * STG_HALVES;
        const __half* bs = as + TILE_HALVES;
        #pragma unroll
        for (int ks = 0; ks < 4; ks++) {
            const int kk = ks * 16 + 2 * t;
            uint32_t af[4][4], bf[4][2];
            #pragma unroll
            for (int i = 0; i < 4; i++) {
                const int r = arow0 + i * 16;
                af[i][0] = *(const uint32_t*)(as + (r    ) * T_STRIDE + kk);
                af[i][1] = *(const uint32_t*)(as + (r + 8) * T_STRIDE + kk);
                af[i][2] = *(const uint32_t*)(as + (r    ) * T_STRIDE + kk + 8);
                af[i][3] = *(const uint32_t*)(as + (r + 8) * T_STRIDE + kk + 8);
            }
            #pragma unroll
            for (int j = 0; j < 4; j++) {
                const int n = bcol0 + j * 8;
                bf[j][0] = *(const uint32_t*)(bs + n * T_STRIDE + kk);
                bf[j][1] = *(const uint32_t*)(bs + n * T_STRIDE + kk + 8);
            }
            #pragma unroll
            for (int i = 0; i < 4; i++)
                #pragma unroll
                for (int j = 0; j < 4; j++)
                    mma_f16(acc[i][j], af[i], bf[j]);
        }
    }

    const int erow = rowbase + warpM * 64 + g;
    const int ecol = colbase + warpN * 32 + 2 * t;
    #pragma unroll
    for (int i = 0; i < 4; i++) {
        #pragma unroll
        for (int j = 0; j < 4; j++) {
            const int r0 = erow + i * 16;
            const int c0 = ecol + j * 8;
            const float b0 = bias[c0], b1 = bias[c0 + 1];
            if (RND) {
                __half* C = (__half*)Cv;
                *(uint32_t*)(C + (size_t)r0 * N + c0)       = pack_h2(acc[i][j][0] + b0, acc[i][j][1] + b1);
                *(uint32_t*)(C + (size_t)(r0 + 8) * N + c0) = pack_h2(acc[i][j][2] + b0, acc[i][j][3] + b1);
            } else {
                float* C = (float*)Cv;
                float2 v0 = { acc[i][j][0] + b0, acc[i][j][1] + b1 };
                float2 v1 = { acc[i][j][2] + b0, acc[i][j][3] + b1 };
                *(float2*)(C + (size_t)r0 * N + c0)       = v0;
                *(float2*)(C + (size_t)(r0 + 8) * N + c0) = v1;
            }
        }
    }
}

// ---------------------------------------------------------------------------
// fp16 flash attention with REGISTER-DIRECT P: the S-mma C-fragment is
// bit-identical to the PV-mma A-fragment (pa[0..3] = packed sc of blocks
// 2ks, 2ks+1) -- no smem staging, no extra syncs. K from qkv, V from vT.
// CTA = 128 q rows of one (b,h); 8 warps x 16 rows. K-tile = 64 keys.
// ---------------------------------------------------------------------------
#define AQ 128
#define AK 64
#define HS 72                              // padded stride (halves)
#define K_HALVES (AK * HS)                 // 4608
#define V_HALVES (HDIM * HS)               // 4608
#define KV_HALVES (K_HALVES + V_HALVES)    // 9216 per stage
#define ATTN_SMEM (2 * KV_HALVES * 2)      // 36864 B

__global__ __launch_bounds__(256)
void attn_h_kernel(const __half* __restrict__ qkv, const __half* __restrict__ vT,
                   __half* __restrict__ out)
{
    extern __shared__ char smem_raw[];
    __half* sm = (__half*)smem_raw;

    const int qtile = gridDim.x - 1 - blockIdx.x;   // heavy tiles first
    const int h   = blockIdx.y;
    const int b   = blockIdx.z;
    const int tid = threadIdx.x;
    const int wid = tid >> 5;
    const int l   = tid & 31;
    const int g   = l >> 2;
    const int t   = l & 3;
    const int qb  = qtile * AQ;
    const int rg  = qb + wid * 16 + g;

    const float SC = 0.18033688011112042f;   // (1/sqrt(64)) * log2(e)
    const uint32_t smb = smem_u32(sm);

    auto load_kv = [&](int stg, int kb) {
        const uint32_t kbuf = smb + (uint32_t)(stg * KV_HALVES) * 2;
        const uint32_t vbuf = kbuf + (uint32_t)K_HALVES * 2;
        #pragma unroll
        for (int it = 0; it < 2; it++) {
            const int idx = it * 256 + tid;
            const int r  = idx >> 3;           // 0..63
            const int c8 = (idx & 7) * 8;      // 0..56
            CP_ASYNC16(kbuf + (uint32_t)(r * HS + c8) * 2,
                       qkv + (size_t)(b * SEQ + kb + r) * C3 + CDIM + h * HDIM + c8);
            CP_ASYNC16(vbuf + (uint32_t)(r * HS + c8) * 2,
                       vT + ((size_t)(b * NHEAD + h) * HDIM + r) * SEQ + kb + c8);
        }
        CP_COMMIT();
    };

    // Q fragments (fp16 pairs), softmax scale folded
    uint32_t qa[4][4];
    {
        const __half* Qr  = qkv + (size_t)(b * SEQ + rg    ) * C3 + h * HDIM;
        const __half* Qr8 = qkv + (size_t)(b * SEQ + rg + 8) * C3 + h * HDIM;
        #pragma unroll
        for (int ks = 0; ks < 4; ks++) {
            #pragma unroll
            for (int q = 0; q < 4; q++) {
                const __half* src = (q & 1) ? Qr8 : Qr;
                const int off = ks * 16 + 2 * t + ((q >> 1) ? 8 : 0);
                __half2 hv = *(const __half2*)(src + off);
                float2 fv = __half22float2(hv);
                qa[ks][q] = pack_h2(fv.x * SC, fv.y * SC);
            }
        }
    }

    float O[8][4];
    #pragma unroll
    for (int nb = 0; nb < 8; nb++)
        #pragma unroll
        for (int q = 0; q < 4; q++) O[nb][q] = 0.f;
    float m0 = -INFINITY, m1 = -INFINITY, l0 = 0.f, l1 = 0.f;

    const int ntiles = (qb + AQ) / AK;

    load_kv(0, 0);
    if (ntiles > 1) load_kv(1, AK);

    for (int ti = 0; ti < ntiles; ti++) {
        if (ti + 1 < ntiles) { CP_WAIT1(); } else { CP_WAIT0(); }
        __syncthreads();

        const __half* Ksm = sm + (ti & 1) * KV_HALVES;
        const __half* Vsm = Ksm + K_HALVES;
        const int kb = ti * AK;

        // S = Q @ K^T (scaled, log2 domain)
        float sc[8][4];
        #pragma unroll
        for (int nb = 0; nb < 8; nb++) {
            sc[nb][0] = 0.f; sc[nb][1] = 0.f; sc[nb][2] = 0.f; sc[nb][3] = 0.f;
        }
        #pragma unroll
        for (int ks = 0; ks < 4; ks++) {
            const int kk = ks * 16 + 2 * t;
            #pragma unroll
            for (int nb = 0; nb < 8; nb++) {
                uint32_t bf[2];
                bf[0] = *(const uint32_t*)(Ksm + (nb * 8 + g) * HS + kk);
                bf[1] = *(const uint32_t*)(Ksm + (nb * 8 + g) * HS + kk + 8);
                mma_f16(sc[nb], qa[ks], bf);
            }
        }

        const bool needmask = (kb + AK - 1) > (qb + wid * 16);
        float tm0 = -INFINITY, tm1 = -INFINITY;
        if (needmask) {
            #pragma unroll
            for (int nb = 0; nb < 8; nb++) {
                const int k0 = kb + nb * 8 + 2 * t;
                if (k0     > rg    ) sc[nb][0] = -INFINITY;
                if (k0 + 1 > rg    ) sc[nb][1] = -INFINITY;
                if (k0     > rg + 8) sc[nb][2] = -INFINITY;
                if (k0 + 1 > rg + 8) sc[nb][3] = -INFINITY;
                tm0 = fmaxf(tm0, fmaxf(sc[nb][0], sc[nb][1]));
                tm1 = fmaxf(tm1, fmaxf(sc[nb][2], sc[nb][3]));
            }
        } else {
            #pragma unroll
            for (int nb = 0; nb < 8; nb++) {
                tm0 = fmaxf(tm0, fmaxf(sc[nb][0], sc[nb][1]));
                tm1 = fmaxf(tm1, fmaxf(sc[nb][2], sc[nb][3]));
            }
        }
        tm0 = fmaxf(tm0, __shfl_xor_sync(0xffffffffu, tm0, 1));
        tm0 = fmaxf(tm0, __shfl_xor_sync(0xffffffffu, tm0, 2));
        tm1 = fmaxf(tm1, __shfl_xor_sync(0xffffffffu, tm1, 1));
        tm1 = fmaxf(tm1, __shfl_xor_sync(0xffffffffu, tm1, 2));

        const float nm0 = fmaxf(m0, tm0);
        const float nm1 = fmaxf(m1, tm1);
        const float c0 = fexp2(m0 - nm0);
        const float c1 = fexp2(m1 - nm1);
        l0 *= c0; l1 *= c1;
        #pragma unroll
        for (int nb = 0; nb < 8; nb++) {
            O[nb][0] *= c0; O[nb][1] *= c0;
            O[nb][2] *= c1; O[nb][3] *= c1;
        }
        m0 = nm0; m1 = nm1;

        // p = exp2(s - m); pack DIRECTLY into PV A-fragments (register-only)
        uint32_t pf[8][2];
        #pragma unroll
        for (int nb = 0; nb < 8; nb++) {
            float p0 = fexp2(sc[nb][0] - m0);
            float p1 = fexp2(sc[nb][1] - m0);
            float p2 = fexp2(sc[nb][2] - m1);
            float p3 = fexp2(sc[nb][3] - m1);
            l0 += p0 + p1;
            l1 += p2 + p3;
            pf[nb][0] = pack_h2(p0, p1);   // row g,   cols 2t,2t+1 of block nb
            pf[nb][1] = pack_h2(p2, p3);   // row g+8, cols 2t,2t+1 of block nb
        }

        // O += P @ V   (pa = C-fragment relabeled as A-fragment)
        #pragma unroll
        for (int ks = 0; ks < 4; ks++) {
            const int kk = ks * 16 + 2 * t;
            uint32_t pa[4];
            pa[0] = pf[2 * ks    ][0];
            pa[1] = pf[2 * ks    ][1];
            pa[2] = pf[2 * ks + 1][0];
            pa[3] = pf[2 * ks + 1][1];
            #pragma unroll
            for (int nb = 0; nb < 8; nb++) {
                uint32_t bf[2];
                bf[0] = *(const uint32_t*)(Vsm + (nb * 8 + g) * HS + kk);
                bf[1] = *(const uint32_t*)(Vsm + (nb * 8 + g) * HS + kk + 8);
                mma_f16(O[nb], pa, bf);
            }
        }
        __syncthreads();                      // buffer fully consumed
        if (ti + 2 < ntiles) load_kv(ti & 1, (ti + 2) * AK);
    }

    l0 += __shfl_xor_sync(0xffffffffu, l0, 1);
    l0 += __shfl_xor_sync(0xffffffffu, l0, 2);
    l1 += __shfl_xor_sync(0xffffffffu, l1, 1);
    l1 += __shfl_xor_sync(0xffffffffu, l1, 2);
    const float inv0 = 1.f / l0;
    const float inv1 = 1.f / l1;

    __half* out0 = out + (size_t)(b * SEQ + rg    ) * CDIM + h * HDIM;
    __half* out8 = out + (size_t)(b * SEQ + rg + 8) * CDIM + h * HDIM;
    #pragma unroll
    for (int nb = 0; nb < 8; nb++) {
        *(uint32_t*)(out0 + nb * 8 + 2 * t) = pack_h2(O[nb][0] * inv0, O[nb][1] * inv0);
        *(uint32_t*)(out8 + nb * 8 + 2 * t) = pack_h2(O[nb][2] * inv1, O[nb][3] * inv1);
    }
}

// ---------------------------------------------------------------------------
// Launch
// ---------------------------------------------------------------------------
extern "C" void kernel_launch(void* const* d_in, const int* in_sizes, int n_in,
                              void* d_out, int out_size)
{
    const float* x    = (const float*)d_in[0];
    const float* Wqkv = (const float*)d_in[1];
    const float* bqkv = (const float*)d_in[2];
    const float* Wout = (const float*)d_in[3];
    const float* bout = (const float*)d_in[4];
    float* out = (float*)d_out;

    __half *qkvh, *vT, *attnh, *xh, *wqkvT, *woutT;
    cudaGetSymbolAddress((void**)&qkvh,  g_qkvh);
    cudaGetSymbolAddress((void**)&vT,    g_vT);
    cudaGetSymbolAddress((void**)&attnh, g_attnh);
    cudaGetSymbolAddress((void**)&xh,    g_xh);
    cudaGetSymbolAddress((void**)&wqkvT, g_wqkvT);
    cudaGetSymbolAddress((void**)&woutT, g_woutT);

    static bool attr_set = false;
    if (!attr_set) {
        cudaFuncSetAttribute(gemm_h_kernel<true>,  cudaFuncAttributeMaxDynamicSharedMemorySize, GEMM_SMEM);
        cudaFuncSetAttribute(gemm_h_kernel<false>, cudaFuncAttributeMaxDynamicSharedMemorySize, GEMM_SMEM);
        cudaFuncSetAttribute(attn_h_kernel, cudaFuncAttributeMaxDynamicSharedMemorySize, ATTN_SMEM);
        attr_set = true;
    }

    // 0) Pre-pass: x -> fp16; weights -> fp16 transposed [N][K]
    xconv_kernel<<<(MROWS * CDIM / 8 + 255) / 256, 256>>>(x, xh, MROWS * CDIM / 8);
    {
        dim3 grid(C3 / 32, CDIM / 32);
        wtrans_kernel<<<grid, 256>>>(Wqkv, wqkvT, CDIM, C3);
    }
    {
        dim3 grid(CDIM / 32, CDIM / 32);
        wtrans_kernel<<<grid, 256>>>(Wout, woutT, CDIM, CDIM);
    }

    // 1) QKV projection -> fp16
    {
        dim3 grid(C3 / GBN, MROWS / GBM);
        gemm_h_kernel<true><<<grid, 256, GEMM_SMEM>>>(xh, wqkvT, bqkv, qkvh, MROWS, C3, CDIM);
    }
    // 1b) V transpose -> [b][h][d][t]
    {
        dim3 grid(SEQ / 64, BATCH * NHEAD);
        vtrans_kernel<<<grid, 256>>>(qkvh, vT);
    }
    // 2) Causal flash attention -> fp16
    {
        dim3 grid(SEQ / AQ, NHEAD, BATCH);
        attn_h_kernel<<<grid, 256, ATTN_SMEM>>>(qkvh, vT, attnh);
    }
    // 3) Output projection -> fp32
    {
        dim3 grid(CDIM / GBN, MROWS / GBM);
        gemm_h_kernel<false><<<grid, 256, GEMM_SMEM>>>(attnh, woutT, bout, out, MROWS, CDIM, CDIM);
    }
}